// round 10
// baseline (speedup 1.0000x reference)
#include <cuda_runtime.h>
#include <cstdint>

// NerfModel: masked voxel gather + SH(deg 2) eval.
// Inputs: x [M,3] f32, d [M,3] f32, voxel_grid [200,200,200,28] f32.
// Output: color [M,3] then sigma [M] (out_size = 4*M floats).
//
// R6: R3's best-measured topology (TILE=128, depth-2 cp.async pipeline),
//     single barrier-ordered sbase (saves 2KB smem -> 8 blocks/SM instead
//     of 7), launch_bounds(128,8) to cap regs at 64, streaming stores.
//     DRAM busy is pinned ~74% across all scheduling configs (random-row
//     gather ceiling); this squeezes the last topology margin.

#define SCALE 1.5f
#define GRID_N 200
#define BLK 128
#define TILE 128

__device__ __forceinline__ void stg_cs(float* p, float v) {
    asm volatile("st.global.cs.f32 [%0], %1;\n" :: "l"(p), "f"(v) : "memory");
}

__device__ __forceinline__ int prep_tile(
    const float* __restrict__ x, const float* __restrict__ d,
    int M, int tile, int tid, int* sbase_buf,
    float& dx, float& dy, float& dz)
{
    int ray = tile * TILE + tid;
    int base = -1;
    dx = dy = dz = 0.0f;
    if (ray < M) {
        float x0 = __ldg(&x[3 * ray + 0]);
        float x1 = __ldg(&x[3 * ray + 1]);
        float x2 = __ldg(&x[3 * ray + 2]);
        bool mask = (fabsf(x0) < SCALE) & (fabsf(x1) < SCALE) & (fabsf(x2) < SCALE);
        if (mask) {
            const float step = 2.0f * SCALE / (float)GRID_N;   // 0.015f
            int i0 = (int)(x0 / step + (float)GRID_N * 0.5f);
            int i1 = (int)(x1 / step + (float)GRID_N * 0.5f);
            int i2 = (int)(x2 / step + (float)GRID_N * 0.5f);
            i0 = min(max(i0, 0), GRID_N - 1);
            i1 = min(max(i1, 0), GRID_N - 1);
            i2 = min(max(i2, 0), GRID_N - 1);
            base = ((i0 * GRID_N + i1) * GRID_N + i2) * 7;     // float4 units
            dx = __ldg(&d[3 * ray + 0]);
            dy = __ldg(&d[3 * ray + 1]);
            dz = __ldg(&d[3 * ray + 2]);
        }
    }
    sbase_buf[tid] = base;
    return base;
}

__device__ __forceinline__ void gather_tile(
    const float* __restrict__ vg, const int* sbase_buf,
    float* srec_buf, int tid)
{
    // TILE*7 = 896 slots, BLK=128 threads -> 7 iterations.
    #pragma unroll
    for (int k = 0; k < 7; k++) {
        int s = tid + k * BLK;
        int r = s / 7;
        int q = s - r * 7;
        int b = sbase_buf[r];
        if (b >= 0) {
            const char* src = (const char*)vg + (((size_t)(b + q)) << 4);
            uint32_t dst = (uint32_t)__cvta_generic_to_shared(srec_buf + r * 28 + q * 4);
            asm volatile("cp.async.cg.shared.global [%0], [%1], 16;\n"
                         :: "r"(dst), "l"(src) : "memory");
        }
    }
}

__device__ __forceinline__ void compute_tile(
    float* __restrict__ out, const float* srec_buf,
    int M, int tile, int tid, int base,
    float dx, float dy, float dz)
{
    int ray = tile * TILE + tid;
    if (ray >= M) return;
    float* color = out + 3 * (size_t)ray;
    float* sigma = out + 3 * (size_t)M + ray;
    if (base >= 0) {
        const float4* t4 = (const float4*)(srec_buf + tid * 28);
        float4 v0 = t4[0];
        float4 v1 = t4[1];
        float4 v2 = t4[2];
        float4 v3 = t4[3];
        float4 v4 = t4[4];
        float4 v5 = t4[5];
        float4 v6 = t4[6];

        stg_cs(sigma, fmaxf(v0.x, 0.0f));

        float b0 = 0.282095f;
        float b1 = -0.488603f * dy;
        float b2 = 0.488603f * dz;
        float b3 = -0.488603f * dx;
        float b4 = 1.092548f * dx * dy;
        float b5 = -1.092548f * dy * dz;
        float b6 = 0.315392f * (2.0f * dz * dz - dx * dx - dy * dy);
        float b7 = -1.092548f * dx * dz;
        float b8 = 0.546274f * (dx * dx - dy * dy);

        // k[0..8]  = v0.y v0.z v0.w v1.x v1.y v1.z v1.w v2.x v2.y   (R)
        // k[9..17] = v2.z v2.w v3.x v3.y v3.z v3.w v4.x v4.y v4.z   (G)
        // k[18..26]= v4.w v5.x v5.y v5.z v5.w v6.x v6.y v6.z v6.w   (B)
        float r;
        r = b0 * v0.y;
        r = fmaf(b1, v0.z, r);  r = fmaf(b2, v0.w, r);
        r = fmaf(b3, v1.x, r);  r = fmaf(b4, v1.y, r);
        r = fmaf(b5, v1.z, r);  r = fmaf(b6, v1.w, r);
        r = fmaf(b7, v2.x, r);  r = fmaf(b8, v2.y, r);

        float g;
        g = b0 * v2.z;
        g = fmaf(b1, v2.w, g);  g = fmaf(b2, v3.x, g);
        g = fmaf(b3, v3.y, g);  g = fmaf(b4, v3.z, g);
        g = fmaf(b5, v3.w, g);  g = fmaf(b6, v4.x, g);
        g = fmaf(b7, v4.y, g);  g = fmaf(b8, v4.z, g);

        float b;
        b = b0 * v4.w;
        b = fmaf(b1, v5.x, b);  b = fmaf(b2, v5.y, b);
        b = fmaf(b3, v5.z, b);  b = fmaf(b4, v5.w, b);
        b = fmaf(b5, v6.x, b);  b = fmaf(b6, v6.y, b);
        b = fmaf(b7, v6.z, b);  b = fmaf(b8, v6.w, b);

        stg_cs(&color[0], r);
        stg_cs(&color[1], g);
        stg_cs(&color[2], b);
    } else {
        stg_cs(&color[0], 0.0f);
        stg_cs(&color[1], 0.0f);
        stg_cs(&color[2], 0.0f);
        stg_cs(sigma, 0.0f);
    }
}

__global__ __launch_bounds__(BLK, 8) void nerf_kernel(
    const float* __restrict__ x,
    const float* __restrict__ d,
    const float* __restrict__ vg,
    float* __restrict__ out,
    int M, int ntiles)
{
    __shared__ float srec[2][TILE * 28];   // 2 x 14 KB
    __shared__ int   sbase[TILE];          // reused each iter (barrier-ordered)

    const int tid = threadIdx.x;
    const int stride = gridDim.x;

    int tile0 = blockIdx.x;
    if (tile0 >= ntiles) return;

    // Prolog: tile0 into buffer 0.
    float d0x, d0y, d0z;
    int base0 = prep_tile(x, d, M, tile0, tid, sbase, d0x, d0y, d0z);
    __syncthreads();
    gather_tile(vg, sbase, srec[0], tid);
    asm volatile("cp.async.commit_group;\n" ::: "memory");

    int i = tile0;
    int buf = 0;

    while (i < ntiles) {
        int nexti = i + stride;
        int nbuf = buf ^ 1;

        float d1x = 0.0f, d1y = 0.0f, d1z = 0.0f;
        int base1 = -1;
        // Previous iteration's trailing __syncthreads orders all prior
        // reads of sbase before this write.
        if (nexti < ntiles)
            base1 = prep_tile(x, d, M, nexti, tid, sbase, d1x, d1y, d1z);

        __syncthreads();   // sbase ready; prior compute's srec[nbuf] reads done

        if (nexti < ntiles)
            gather_tile(vg, sbase, srec[nbuf], tid);
        asm volatile("cp.async.commit_group;\n" ::: "memory");   // possibly empty

        asm volatile("cp.async.wait_group 1;\n" ::: "memory");   // tile i's copies done
        __syncthreads();

        // COMPUTE tile i
        compute_tile(out, srec[buf], M, i, tid, base0, d0x, d0y, d0z);

        i = nexti;
        buf = nbuf;
        base0 = base1;
        d0x = d1x; d0y = d1y; d0z = d1z;
    }
}

extern "C" void kernel_launch(void* const* d_in, const int* in_sizes, int n_in,
                              void* d_out, int out_size) {
    const float* x  = (const float*)d_in[0];
    const float* d  = (const float*)d_in[1];
    const float* vg = (const float*)d_in[2];
    float* out = (float*)d_out;

    int M = in_sizes[0] / 3;
    int ntiles = (M + TILE - 1) / TILE;

    // 8 blocks/SM (28.5 KB smem each) on 148 SMs, persistent grid-stride.
    int grid = 148 * 8;
    if (grid > ntiles) grid = ntiles;
    nerf_kernel<<<grid, BLK>>>(x, d, vg, out, M, ntiles);
}

// round 11
// speedup vs baseline: 1.3524x; 1.3524x over previous
#include <cuda_runtime.h>
#include <cstdint>

// NerfModel: masked voxel gather + SH(deg 2) eval.
// Inputs: x [M,3] f32, d [M,3] f32, voxel_grid [200,200,200,28] f32.
// Output: color [M,3] then sigma [M] (out_size = 4*M floats).
//
// R7: revert to the measured-best R3 topology (TILE=128, depth-2 cp.async
//     pipeline, 7 blocks/SM) with only safe cleanups kept:
//       - single barrier-ordered sbase (validated in R5)
//       - normal global stores (R6's st.global.cs + asm memory clobbers
//         and 8-blocks/SM => zero L1D carveout caused the 114us regression)
//     7 x 28.5 KB = 199.5 KB smem leaves ~28 KB L1D for streaming x/d loads.

#define SCALE 1.5f
#define GRID_N 200
#define BLK 128
#define TILE 128

__device__ __forceinline__ int prep_tile(
    const float* __restrict__ x, const float* __restrict__ d,
    int M, int tile, int tid, int* sbase_buf,
    float& dx, float& dy, float& dz)
{
    int ray = tile * TILE + tid;
    int base = -1;
    dx = dy = dz = 0.0f;
    if (ray < M) {
        float x0 = __ldg(&x[3 * ray + 0]);
        float x1 = __ldg(&x[3 * ray + 1]);
        float x2 = __ldg(&x[3 * ray + 2]);
        bool mask = (fabsf(x0) < SCALE) & (fabsf(x1) < SCALE) & (fabsf(x2) < SCALE);
        if (mask) {
            const float step = 2.0f * SCALE / (float)GRID_N;   // 0.015f
            int i0 = (int)(x0 / step + (float)GRID_N * 0.5f);
            int i1 = (int)(x1 / step + (float)GRID_N * 0.5f);
            int i2 = (int)(x2 / step + (float)GRID_N * 0.5f);
            i0 = min(max(i0, 0), GRID_N - 1);
            i1 = min(max(i1, 0), GRID_N - 1);
            i2 = min(max(i2, 0), GRID_N - 1);
            base = ((i0 * GRID_N + i1) * GRID_N + i2) * 7;     // float4 units
            dx = __ldg(&d[3 * ray + 0]);
            dy = __ldg(&d[3 * ray + 1]);
            dz = __ldg(&d[3 * ray + 2]);
        }
    }
    sbase_buf[tid] = base;
    return base;
}

__device__ __forceinline__ void gather_tile(
    const float* __restrict__ vg, const int* sbase_buf,
    float* srec_buf, int tid)
{
    // TILE*7 = 896 slots, BLK=128 threads -> 7 iterations.
    #pragma unroll
    for (int k = 0; k < 7; k++) {
        int s = tid + k * BLK;
        int r = s / 7;
        int q = s - r * 7;
        int b = sbase_buf[r];
        if (b >= 0) {
            const char* src = (const char*)vg + (((size_t)(b + q)) << 4);
            uint32_t dst = (uint32_t)__cvta_generic_to_shared(srec_buf + r * 28 + q * 4);
            asm volatile("cp.async.cg.shared.global [%0], [%1], 16;\n"
                         :: "r"(dst), "l"(src) : "memory");
        }
    }
}

__device__ __forceinline__ void compute_tile(
    float* __restrict__ out, const float* srec_buf,
    int M, int tile, int tid, int base,
    float dx, float dy, float dz)
{
    int ray = tile * TILE + tid;
    if (ray >= M) return;
    float* color = out + 3 * (size_t)ray;
    float* sigma = out + 3 * (size_t)M + ray;
    if (base >= 0) {
        const float4* t4 = (const float4*)(srec_buf + tid * 28);
        float4 v0 = t4[0];
        float4 v1 = t4[1];
        float4 v2 = t4[2];
        float4 v3 = t4[3];
        float4 v4 = t4[4];
        float4 v5 = t4[5];
        float4 v6 = t4[6];

        *sigma = fmaxf(v0.x, 0.0f);

        float b0 = 0.282095f;
        float b1 = -0.488603f * dy;
        float b2 = 0.488603f * dz;
        float b3 = -0.488603f * dx;
        float b4 = 1.092548f * dx * dy;
        float b5 = -1.092548f * dy * dz;
        float b6 = 0.315392f * (2.0f * dz * dz - dx * dx - dy * dy);
        float b7 = -1.092548f * dx * dz;
        float b8 = 0.546274f * (dx * dx - dy * dy);

        // k[0..8]  = v0.y v0.z v0.w v1.x v1.y v1.z v1.w v2.x v2.y   (R)
        // k[9..17] = v2.z v2.w v3.x v3.y v3.z v3.w v4.x v4.y v4.z   (G)
        // k[18..26]= v4.w v5.x v5.y v5.z v5.w v6.x v6.y v6.z v6.w   (B)
        float r;
        r = b0 * v0.y;
        r = fmaf(b1, v0.z, r);  r = fmaf(b2, v0.w, r);
        r = fmaf(b3, v1.x, r);  r = fmaf(b4, v1.y, r);
        r = fmaf(b5, v1.z, r);  r = fmaf(b6, v1.w, r);
        r = fmaf(b7, v2.x, r);  r = fmaf(b8, v2.y, r);

        float g;
        g = b0 * v2.z;
        g = fmaf(b1, v2.w, g);  g = fmaf(b2, v3.x, g);
        g = fmaf(b3, v3.y, g);  g = fmaf(b4, v3.z, g);
        g = fmaf(b5, v3.w, g);  g = fmaf(b6, v4.x, g);
        g = fmaf(b7, v4.y, g);  g = fmaf(b8, v4.z, g);

        float b;
        b = b0 * v4.w;
        b = fmaf(b1, v5.x, b);  b = fmaf(b2, v5.y, b);
        b = fmaf(b3, v5.z, b);  b = fmaf(b4, v5.w, b);
        b = fmaf(b5, v6.x, b);  b = fmaf(b6, v6.y, b);
        b = fmaf(b7, v6.z, b);  b = fmaf(b8, v6.w, b);

        color[0] = r;
        color[1] = g;
        color[2] = b;
    } else {
        color[0] = 0.0f;
        color[1] = 0.0f;
        color[2] = 0.0f;
        *sigma = 0.0f;
    }
}

__global__ __launch_bounds__(BLK) void nerf_kernel(
    const float* __restrict__ x,
    const float* __restrict__ d,
    const float* __restrict__ vg,
    float* __restrict__ out,
    int M, int ntiles)
{
    __shared__ float srec[2][TILE * 28];   // 2 x 14 KB
    __shared__ int   sbase[TILE];          // reused each iter (barrier-ordered)

    const int tid = threadIdx.x;
    const int stride = gridDim.x;

    int tile0 = blockIdx.x;
    if (tile0 >= ntiles) return;

    // Prolog: tile0 into buffer 0.
    float d0x, d0y, d0z;
    int base0 = prep_tile(x, d, M, tile0, tid, sbase, d0x, d0y, d0z);
    __syncthreads();
    gather_tile(vg, sbase, srec[0], tid);
    asm volatile("cp.async.commit_group;\n" ::: "memory");

    int i = tile0;
    int buf = 0;

    while (i < ntiles) {
        int nexti = i + stride;
        int nbuf = buf ^ 1;

        float d1x = 0.0f, d1y = 0.0f, d1z = 0.0f;
        int base1 = -1;
        // Previous iteration's trailing __syncthreads orders all prior
        // reads of sbase before this write.
        if (nexti < ntiles)
            base1 = prep_tile(x, d, M, nexti, tid, sbase, d1x, d1y, d1z);

        __syncthreads();   // sbase ready; prior compute's srec[nbuf] reads done

        if (nexti < ntiles)
            gather_tile(vg, sbase, srec[nbuf], tid);
        asm volatile("cp.async.commit_group;\n" ::: "memory");   // possibly empty

        asm volatile("cp.async.wait_group 1;\n" ::: "memory");   // tile i's copies done
        __syncthreads();

        // COMPUTE tile i
        compute_tile(out, srec[buf], M, i, tid, base0, d0x, d0y, d0z);

        i = nexti;
        buf = nbuf;
        base0 = base1;
        d0x = d1x; d0y = d1y; d0z = d1z;
    }
}

extern "C" void kernel_launch(void* const* d_in, const int* in_sizes, int n_in,
                              void* d_out, int out_size) {
    const float* x  = (const float*)d_in[0];
    const float* d  = (const float*)d_in[1];
    const float* vg = (const float*)d_in[2];
    float* out = (float*)d_out;

    int M = in_sizes[0] / 3;
    int ntiles = (M + TILE - 1) / TILE;

    // 7 blocks/SM (28.5 KB smem each -> 199.5 KB, keeps ~28 KB L1D),
    // persistent grid-stride on 148 SMs.
    int grid = 148 * 7;
    if (grid > ntiles) grid = ntiles;
    nerf_kernel<<<grid, BLK>>>(x, d, vg, out, M, ntiles);
}